// round 1
// baseline (speedup 1.0000x reference)
#include <cuda_runtime.h>

// NeuralODE: z' = tanh(z@W1+b1)@W2 + b2, RK4 over 127 intervals.
// BS=1024, ZDIM=HID=256, TLEN=128.
//
// Persistent design: 128 CTAs x 256 threads; each CTA owns 8 batch rows and
// integrates all 127 RK4 steps with no global sync (rows are independent).
// Weights stream from L2 (512KB resident); activations live in SMEM.
// Thread c computes column c for all 8 rows (coalesced W[k][c] reads),
// with a 4-deep register prefetch pipeline on W to hide L2 latency.

#define ZDIM 256
#define HID 256
#define TLEN 128
#define MT 8          // rows per CTA
#define NCTA 128      // 1024 / MT

__device__ __forceinline__ void gemm_tile(const float (*__restrict__ in_s)[ZDIM],
                                          const float* __restrict__ W,
                                          float bias,
                                          float (*__restrict__ out_s)[ZDIM],
                                          bool dotanh, int c)
{
    float acc[MT];
#pragma unroll
    for (int r = 0; r < MT; r++) acc[r] = bias;

    // 4-stage register prefetch of W columns (4 k-rows per stage).
    float wb[4][4];
#pragma unroll
    for (int sg = 0; sg < 4; sg++)
#pragma unroll
        for (int i = 0; i < 4; i++)
            wb[sg][i] = W[(4 * sg + i) * ZDIM + c];

    for (int kb4 = 0; kb4 < 16; kb4++) {
#pragma unroll
        for (int j = 0; j < 4; j++) {
            const int kb = kb4 * 4 + j;           // k-block index (4 k's each)
            const float w0 = wb[j][0];
            const float w1 = wb[j][1];
            const float w2 = wb[j][2];
            const float w3 = wb[j][3];
            const int kpf = kb + 4;               // prefetch 4 blocks ahead
            if (kpf < 64) {
#pragma unroll
                for (int i = 0; i < 4; i++)
                    wb[j][i] = W[(4 * kpf + i) * ZDIM + c];
            }
#pragma unroll
            for (int r = 0; r < MT; r++) {
                const float4 zv =
                    *reinterpret_cast<const float4*>(&in_s[r][4 * kb]);
                acc[r] = fmaf(zv.x, w0, acc[r]);
                acc[r] = fmaf(zv.y, w1, acc[r]);
                acc[r] = fmaf(zv.z, w2, acc[r]);
                acc[r] = fmaf(zv.w, w3, acc[r]);
            }
        }
    }

#pragma unroll
    for (int r = 0; r < MT; r++)
        out_s[r][c] = dotanh ? tanhf(acc[r]) : acc[r];
}

__global__ void __launch_bounds__(256, 1)
node_kernel(const float* __restrict__ z0, const float* __restrict__ t,
            const float* __restrict__ W1, const float* __restrict__ b1,
            const float* __restrict__ W2, const float* __restrict__ b2,
            float* __restrict__ out)
{
    __shared__ __align__(16) float sz[MT][ZDIM];    // current state z
    __shared__ __align__(16) float sacc[MT][ZDIM];  // accumulating z_{n+1}
    __shared__ __align__(16) float sst[MT][ZDIM];   // staged input to f
    __shared__ __align__(16) float sh[MT][HID];     // tanh hidden
    __shared__ __align__(16) float sf[MT][ZDIM];    // f output (k_i)

    const int c = threadIdx.x;                      // column 0..255
    const int row0 = blockIdx.x * MT;

#pragma unroll
    for (int r = 0; r < MT; r++)
        sz[r][c] = z0[(row0 + r) * ZDIM + c];

    const float bb1 = b1[c];
    const float bb2 = b2[c];
    __syncthreads();

    for (int s = 0; s < TLEN - 1; s++) {
        const float hs = t[s + 1] - t[s];

        // ---- k1 = f(z) ----
        gemm_tile(sz, W1, bb1, sh, true, c);   __syncthreads();
        gemm_tile(sh, W2, bb2, sf, false, c);  __syncthreads();
#pragma unroll
        for (int r = 0; r < MT; r++) {
            const float z = sz[r][c], k = sf[r][c];
            sacc[r][c] = fmaf(hs * (1.0f / 6.0f), k, z);
            sst[r][c]  = fmaf(hs * 0.5f, k, z);
        }
        __syncthreads();

        // ---- k2 = f(z + h/2 * k1) ----
        gemm_tile(sst, W1, bb1, sh, true, c);  __syncthreads();
        gemm_tile(sh, W2, bb2, sf, false, c);  __syncthreads();
#pragma unroll
        for (int r = 0; r < MT; r++) {
            const float z = sz[r][c], k = sf[r][c];
            sacc[r][c] = fmaf(hs * (1.0f / 3.0f), k, sacc[r][c]);
            sst[r][c]  = fmaf(hs * 0.5f, k, z);
        }
        __syncthreads();

        // ---- k3 = f(z + h/2 * k2) ----
        gemm_tile(sst, W1, bb1, sh, true, c);  __syncthreads();
        gemm_tile(sh, W2, bb2, sf, false, c);  __syncthreads();
#pragma unroll
        for (int r = 0; r < MT; r++) {
            const float z = sz[r][c], k = sf[r][c];
            sacc[r][c] = fmaf(hs * (1.0f / 3.0f), k, sacc[r][c]);
            sst[r][c]  = fmaf(hs, k, z);
        }
        __syncthreads();

        // ---- k4 = f(z + h * k3) ; z <- z_{n+1} ----
        gemm_tile(sst, W1, bb1, sh, true, c);  __syncthreads();
        gemm_tile(sh, W2, bb2, sf, false, c);  __syncthreads();
#pragma unroll
        for (int r = 0; r < MT; r++) {
            const float k = sf[r][c];
            sz[r][c] = fmaf(hs * (1.0f / 6.0f), k, sacc[r][c]);
        }
        __syncthreads();
    }

#pragma unroll
    for (int r = 0; r < MT; r++)
        out[(row0 + r) * ZDIM + c] = sz[r][c];
}

extern "C" void kernel_launch(void* const* d_in, const int* in_sizes, int n_in,
                              void* d_out, int out_size)
{
    const float* z0 = (const float*)d_in[0];
    const float* t  = (const float*)d_in[1];
    const float* W1 = (const float*)d_in[2];
    const float* b1 = (const float*)d_in[3];
    const float* W2 = (const float*)d_in[4];
    const float* b2 = (const float*)d_in[5];
    float* out = (float*)d_out;

    node_kernel<<<NCTA, 256>>>(z0, t, W1, b1, W2, b2, out);
}

// round 2
// speedup vs baseline: 1.6810x; 1.6810x over previous
#include <cuda_runtime.h>
#include <stdint.h>

// NeuralODE RK4 via tensor cores (tf32 mma.sync), sm_103a.
// 64 CTAs x 256 threads; each CTA owns 16 batch rows, all 127 RK4 steps.
// W1/W2 pre-swizzled into B-fragment layout (tf32) by a prep kernel.
// Activations (A operand) in SMEM as tf32; z-state & RK4 accumulator in regs.

#define ZDIM 256
#define TLEN 128
#define MROW 16          // rows per CTA
#define NCTA 64          // 1024/16
#define SP   260         // smem row stride (floats): 260 % 32 == 4 -> conflict-free A frags
#define NKT  32          // K / 8
#define NNT  32          // N / 8
#define WSEG (NKT * NNT * 32)   // uint2 elements per weight matrix

__device__ uint2 Wf_scratch[2 * WSEG];   // 512 KB fragment-layout weights (tf32)

__device__ __forceinline__ unsigned tf32_of(float f) {
    unsigned u;
    asm("cvt.rna.tf32.f32 %0, %1;" : "=r"(u) : "f"(f));
    return u;
}

// ---------------- prep: W[k][n] row-major -> B-fragment layout ----------------
// Wf[((g*NKT + kt)*NNT + nt)*32 + lane] = { tf32(W[kt*8 + lane%4][nt*8 + lane/4]),
//                                           tf32(W[kt*8 + lane%4 + 4][nt*8 + lane/4]) }
__global__ void prep_kernel(const float* __restrict__ W1, const float* __restrict__ W2)
{
    int idx = blockIdx.x * blockDim.x + threadIdx.x;
    if (idx >= 2 * WSEG) return;
    int lane = idx & 31;
    int nt   = (idx >> 5) & 31;
    int kt   = (idx >> 10) & 31;
    int g    = idx >> 15;
    const float* W = g ? W2 : W1;
    int k0 = kt * 8 + (lane & 3);
    int n  = nt * 8 + (lane >> 2);
    uint2 v;
    v.x = tf32_of(W[k0 * ZDIM + n]);
    v.y = tf32_of(W[(k0 + 4) * ZDIM + n]);
    Wf_scratch[idx] = v;
}

// ---------------- one [16,256] @ [256,256] GEMM on tensor cores ----------------
__device__ __forceinline__ void gemm_mma(const unsigned* __restrict__ A,     // smem [16][SP] tf32
                                         const uint2* __restrict__ Wfg,     // fragment weights
                                         const float* __restrict__ bias_s,  // smem [256]
                                         int lane, int nt0, float acc[4][4])
{
    const int r0 = lane >> 2;
    const int c0 = lane & 3;

#pragma unroll
    for (int t = 0; t < 4; t++) {
        float bb0 = bias_s[(nt0 + t) * 8 + 2 * c0];
        float bb1 = bias_s[(nt0 + t) * 8 + 2 * c0 + 1];
        acc[t][0] = bb0; acc[t][1] = bb1; acc[t][2] = bb0; acc[t][3] = bb1;
    }

    uint2 bb[4];
#pragma unroll
    for (int t = 0; t < 4; t++)
        bb[t] = Wfg[(0 * NNT + nt0 + t) * 32 + lane];

#pragma unroll 4
    for (int kt = 0; kt < NKT; kt++) {
        uint2 bn[4];
        if (kt < NKT - 1) {
#pragma unroll
            for (int t = 0; t < 4; t++)
                bn[t] = Wfg[((kt + 1) * NNT + nt0 + t) * 32 + lane];
        }
        const unsigned* Ak = A + kt * 8;
        unsigned a0 = Ak[r0 * SP + c0];
        unsigned a1 = Ak[(r0 + 8) * SP + c0];
        unsigned a2 = Ak[r0 * SP + c0 + 4];
        unsigned a3 = Ak[(r0 + 8) * SP + c0 + 4];
#pragma unroll
        for (int t = 0; t < 4; t++) {
            asm volatile(
                "mma.sync.aligned.m16n8k8.row.col.f32.tf32.tf32.f32 "
                "{%0,%1,%2,%3}, {%4,%5,%6,%7}, {%8,%9}, {%0,%1,%2,%3};"
                : "+f"(acc[t][0]), "+f"(acc[t][1]), "+f"(acc[t][2]), "+f"(acc[t][3])
                : "r"(a0), "r"(a1), "r"(a2), "r"(a3), "r"(bb[t].x), "r"(bb[t].y));
        }
        if (kt < NKT - 1) {
#pragma unroll
            for (int t = 0; t < 4; t++) bb[t] = bn[t];
        }
    }
}

// f(z) = tanh(z@W1+b1)@W2+b2 ; A-operand already staged in Atf; result in kf.
__device__ __forceinline__ void feval(const unsigned* Atf, unsigned* Htf,
                                      const float* b1s, const float* b2s,
                                      const uint2* Wf1, const uint2* Wf2,
                                      int lane, int nt0, int r0, int c0,
                                      float kf[4][4])
{
    float acc[4][4];
    gemm_mma(Atf, Wf1, b1s, lane, nt0, acc);
#pragma unroll
    for (int t = 0; t < 4; t++) {
        int cb = (nt0 + t) * 8 + 2 * c0;
        Htf[r0 * SP + cb]           = tf32_of(tanhf(acc[t][0]));
        Htf[r0 * SP + cb + 1]       = tf32_of(tanhf(acc[t][1]));
        Htf[(r0 + 8) * SP + cb]     = tf32_of(tanhf(acc[t][2]));
        Htf[(r0 + 8) * SP + cb + 1] = tf32_of(tanhf(acc[t][3]));
    }
    __syncthreads();
    gemm_mma(Htf, Wf2, b2s, lane, nt0, kf);
}

__global__ void __launch_bounds__(256, 1)
node_kernel(const float* __restrict__ z0, const float* __restrict__ tg,
            const float* __restrict__ b1, const float* __restrict__ b2,
            float* __restrict__ out)
{
    __shared__ unsigned Atf[MROW * SP];
    __shared__ unsigned Htf[MROW * SP];
    __shared__ float b1s[ZDIM];
    __shared__ float b2s[ZDIM];

    const int tid  = threadIdx.x;
    const int lane = tid & 31;
    const int wid  = tid >> 5;           // 0..7
    const int nt0  = wid * 4;            // 4 n-tiles per warp
    const int r0   = lane >> 2;
    const int c0   = lane & 3;
    const int row0 = blockIdx.x * MROW;

    const uint2* Wf1 = Wf_scratch;
    const uint2* Wf2 = Wf_scratch + WSEG;

    if (tid < ZDIM) { b1s[tid] = b1[tid]; b2s[tid] = b2[tid]; }

    // Thread-owned output coords: rows {r0, r0+8}, cols {cb, cb+1} per n-tile t.
    float zr[4][4];   // z state (fp32)
    float ar[4][4];   // RK4 accumulator
#pragma unroll
    for (int t = 0; t < 4; t++) {
        int cb = (nt0 + t) * 8 + 2 * c0;
        zr[t][0] = z0[(row0 + r0) * ZDIM + cb];
        zr[t][1] = z0[(row0 + r0) * ZDIM + cb + 1];
        zr[t][2] = z0[(row0 + r0 + 8) * ZDIM + cb];
        zr[t][3] = z0[(row0 + r0 + 8) * ZDIM + cb + 1];
        Atf[r0 * SP + cb]           = tf32_of(zr[t][0]);
        Atf[r0 * SP + cb + 1]       = tf32_of(zr[t][1]);
        Atf[(r0 + 8) * SP + cb]     = tf32_of(zr[t][2]);
        Atf[(r0 + 8) * SP + cb + 1] = tf32_of(zr[t][3]);
    }
    __syncthreads();

    float kf[4][4];
    for (int s = 0; s < TLEN - 1; s++) {
        const float hs = tg[s + 1] - tg[s];
        const float h6 = hs * (1.0f / 6.0f);
        const float h3 = hs * (1.0f / 3.0f);
        const float h2 = hs * 0.5f;

        // ---- k1 ----
        feval(Atf, Htf, b1s, b2s, Wf1, Wf2, lane, nt0, r0, c0, kf);
#pragma unroll
        for (int t = 0; t < 4; t++) {
            int cb = (nt0 + t) * 8 + 2 * c0;
#pragma unroll
            for (int d = 0; d < 4; d++) {
                ar[t][d] = fmaf(h6, kf[t][d], zr[t][d]);
                float st = fmaf(h2, kf[t][d], zr[t][d]);
                int rr = r0 + ((d >> 1) << 3);
                Atf[rr * SP + cb + (d & 1)] = tf32_of(st);
            }
        }
        __syncthreads();

        // ---- k2 ----
        feval(Atf, Htf, b1s, b2s, Wf1, Wf2, lane, nt0, r0, c0, kf);
#pragma unroll
        for (int t = 0; t < 4; t++) {
            int cb = (nt0 + t) * 8 + 2 * c0;
#pragma unroll
            for (int d = 0; d < 4; d++) {
                ar[t][d] = fmaf(h3, kf[t][d], ar[t][d]);
                float st = fmaf(h2, kf[t][d], zr[t][d]);
                int rr = r0 + ((d >> 1) << 3);
                Atf[rr * SP + cb + (d & 1)] = tf32_of(st);
            }
        }
        __syncthreads();

        // ---- k3 ----
        feval(Atf, Htf, b1s, b2s, Wf1, Wf2, lane, nt0, r0, c0, kf);
#pragma unroll
        for (int t = 0; t < 4; t++) {
            int cb = (nt0 + t) * 8 + 2 * c0;
#pragma unroll
            for (int d = 0; d < 4; d++) {
                ar[t][d] = fmaf(h3, kf[t][d], ar[t][d]);
                float st = fmaf(hs, kf[t][d], zr[t][d]);
                int rr = r0 + ((d >> 1) << 3);
                Atf[rr * SP + cb + (d & 1)] = tf32_of(st);
            }
        }
        __syncthreads();

        // ---- k4 + state update ----
        feval(Atf, Htf, b1s, b2s, Wf1, Wf2, lane, nt0, r0, c0, kf);
#pragma unroll
        for (int t = 0; t < 4; t++) {
            int cb = (nt0 + t) * 8 + 2 * c0;
#pragma unroll
            for (int d = 0; d < 4; d++) {
                zr[t][d] = fmaf(h6, kf[t][d], ar[t][d]);
                int rr = r0 + ((d >> 1) << 3);
                Atf[rr * SP + cb + (d & 1)] = tf32_of(zr[t][d]);
            }
        }
        __syncthreads();
    }

#pragma unroll
    for (int t = 0; t < 4; t++) {
        int cb = (nt0 + t) * 8 + 2 * c0;
        out[(row0 + r0) * ZDIM + cb]         = zr[t][0];
        out[(row0 + r0) * ZDIM + cb + 1]     = zr[t][1];
        out[(row0 + r0 + 8) * ZDIM + cb]     = zr[t][2];
        out[(row0 + r0 + 8) * ZDIM + cb + 1] = zr[t][3];
    }
}

extern "C" void kernel_launch(void* const* d_in, const int* in_sizes, int n_in,
                              void* d_out, int out_size)
{
    const float* z0 = (const float*)d_in[0];
    const float* t  = (const float*)d_in[1];
    const float* W1 = (const float*)d_in[2];
    const float* b1 = (const float*)d_in[3];
    const float* W2 = (const float*)d_in[4];
    const float* b2 = (const float*)d_in[5];
    float* out = (float*)d_out;

    prep_kernel<<<(2 * WSEG + 255) / 256, 256>>>(W1, W2);
    node_kernel<<<NCTA, 256>>>(z0, t, b1, b2, out);
}

// round 3
// speedup vs baseline: 3.9869x; 2.3718x over previous
#include <cuda_runtime.h>
#include <cuda_fp16.h>
#include <stdint.h>

// NeuralODE RK4, fp16 tensor cores (mma.m16n8k16.f16, fp32 accum), sm_103a.
// 64 CTAs x 512 threads (16 warps); CTA owns 16 batch rows, all 127 steps.
// W1/W2 pre-swizzled once into fp16 B-fragment layout (256 KB total, L2-resident).
// Each warp owns 2 n-tiles (16 of the 256 output cols); activations staged in
// SMEM as half2; z-state + RK4 accumulator in fp32 registers.

#define ZDIM 256
#define TLEN 128
#define MROW 16
#define NCTA 64
#define NKT  16           // K/16
#define NNT  32           // N/8
#define ASP  132          // A smem row stride in half2 words (128 + 4 pad)
#define NWREC (2 * NKT * NNT * 32)

__device__ uint2 Wf[NWREC];   // 256 KB fp16 fragment-layout weights

// ---- prep: W[k][n] row-major fp32 -> fp16 B-fragment layout ----
__global__ void prep_kernel(const float* __restrict__ W1, const float* __restrict__ W2)
{
    int idx = blockIdx.x * blockDim.x + threadIdx.x;
    if (idx >= NWREC) return;
    int lane = idx & 31;
    int nt   = (idx >> 5) & 31;
    int kt   = (idx >> 10) & 15;
    int g    = idx >> 14;
    const float* W = g ? W2 : W1;
    int k0 = kt * 16 + 2 * (lane & 3);
    int n  = nt * 8 + (lane >> 2);
    __half2 lo = __floats2half2_rn(W[k0 * ZDIM + n],       W[(k0 + 1) * ZDIM + n]);
    __half2 hi = __floats2half2_rn(W[(k0 + 8) * ZDIM + n], W[(k0 + 9) * ZDIM + n]);
    uint2 v;
    v.x = *reinterpret_cast<unsigned*>(&lo);
    v.y = *reinterpret_cast<unsigned*>(&hi);
    Wf[idx] = v;
}

// ---- one [16,256]x[256,256] GEMM; this warp produces n-tiles nt0, nt0+1 ----
__device__ __forceinline__ void gemm16(const unsigned* __restrict__ As,   // [16][ASP] half2
                                       const uint2* __restrict__ Wg,      // fragment weights
                                       int lane, int nt0,
                                       const float bias[2][2],
                                       float acc[2][4])
{
    const int r0 = lane >> 2;
    const int c0 = lane & 3;
#pragma unroll
    for (int t = 0; t < 2; t++) {
        acc[t][0] = bias[t][0]; acc[t][1] = bias[t][1];
        acc[t][2] = bias[t][0]; acc[t][3] = bias[t][1];
    }

    // 8-kt-deep register prefetch window for B (16 LDG.64 in flight).
    uint2 bw[8][2];
#pragma unroll
    for (int kt = 0; kt < 8; kt++)
#pragma unroll
        for (int t = 0; t < 2; t++)
            bw[kt][t] = Wg[(kt * NNT + nt0 + t) * 32 + lane];

#pragma unroll
    for (int kt = 0; kt < NKT; kt++) {
        const unsigned* Ak = As + kt * 8;
        unsigned a0 = Ak[r0 * ASP + c0];
        unsigned a1 = Ak[(r0 + 8) * ASP + c0];
        unsigned a2 = Ak[r0 * ASP + c0 + 4];
        unsigned a3 = Ak[(r0 + 8) * ASP + c0 + 4];
        uint2 b0 = bw[kt & 7][0];
        uint2 b1 = bw[kt & 7][1];
        if (kt + 8 < NKT) {
#pragma unroll
            for (int t = 0; t < 2; t++)
                bw[kt & 7][t] = Wg[((kt + 8) * NNT + nt0 + t) * 32 + lane];
        }
        asm volatile("mma.sync.aligned.m16n8k16.row.col.f32.f16.f16.f32 "
                     "{%0,%1,%2,%3}, {%4,%5,%6,%7}, {%8,%9}, {%0,%1,%2,%3};"
                     : "+f"(acc[0][0]), "+f"(acc[0][1]), "+f"(acc[0][2]), "+f"(acc[0][3])
                     : "r"(a0), "r"(a1), "r"(a2), "r"(a3), "r"(b0.x), "r"(b0.y));
        asm volatile("mma.sync.aligned.m16n8k16.row.col.f32.f16.f16.f32 "
                     "{%0,%1,%2,%3}, {%4,%5,%6,%7}, {%8,%9}, {%0,%1,%2,%3};"
                     : "+f"(acc[1][0]), "+f"(acc[1][1]), "+f"(acc[1][2]), "+f"(acc[1][3])
                     : "r"(a0), "r"(a1), "r"(a2), "r"(a3), "r"(b1.x), "r"(b1.y));
    }
}

// f(z): GEMM1 -> tanh -> Htf -> sync -> GEMM2 -> kf
__device__ __forceinline__ void feval(const unsigned* Atf, unsigned* Htf,
                                      const uint2* Wf1, const uint2* Wf2,
                                      const float bias1[2][2], const float bias2[2][2],
                                      int lane, int nt0, int r0, int c0,
                                      float kf[2][4])
{
    float acc[2][4];
    gemm16(Atf, Wf1, lane, nt0, bias1, acc);
#pragma unroll
    for (int t = 0; t < 2; t++) {
        int cu = (nt0 + t) * 4 + c0;             // half2 col index
        __half2 lo = __floats2half2_rn(tanhf(acc[t][0]), tanhf(acc[t][1]));
        __half2 hi = __floats2half2_rn(tanhf(acc[t][2]), tanhf(acc[t][3]));
        Htf[r0 * ASP + cu]       = *reinterpret_cast<unsigned*>(&lo);
        Htf[(r0 + 8) * ASP + cu] = *reinterpret_cast<unsigned*>(&hi);
    }
    __syncthreads();
    gemm16(Htf, Wf2, lane, nt0, bias2, kf);
}

__global__ void __launch_bounds__(512, 1)
node_kernel(const float* __restrict__ z0, const float* __restrict__ tg,
            const float* __restrict__ b1, const float* __restrict__ b2,
            float* __restrict__ out)
{
    __shared__ unsigned Atf[MROW * ASP];
    __shared__ unsigned Htf[MROW * ASP];

    const int tid  = threadIdx.x;
    const int lane = tid & 31;
    const int wid  = tid >> 5;           // 0..15
    const int nt0  = wid * 2;            // 2 n-tiles per warp
    const int r0   = lane >> 2;
    const int c0   = lane & 3;
    const int row0 = blockIdx.x * MROW;

    const uint2* Wf1 = Wf;
    const uint2* Wf2 = Wf + (NWREC / 2);

    float bias1[2][2], bias2[2][2];
#pragma unroll
    for (int t = 0; t < 2; t++) {
        int cb = (nt0 + t) * 8 + 2 * c0;
        bias1[t][0] = b1[cb]; bias1[t][1] = b1[cb + 1];
        bias2[t][0] = b2[cb]; bias2[t][1] = b2[cb + 1];
    }

    float zr[2][4], ar[2][4], kf[2][4];
#pragma unroll
    for (int t = 0; t < 2; t++) {
        int cb = (nt0 + t) * 8 + 2 * c0;
        float2 v0 = *reinterpret_cast<const float2*>(&z0[(row0 + r0) * ZDIM + cb]);
        float2 v1 = *reinterpret_cast<const float2*>(&z0[(row0 + r0 + 8) * ZDIM + cb]);
        zr[t][0] = v0.x; zr[t][1] = v0.y; zr[t][2] = v1.x; zr[t][3] = v1.y;
        int cu = (nt0 + t) * 4 + c0;
        __half2 lo = __floats2half2_rn(v0.x, v0.y);
        __half2 hi = __floats2half2_rn(v1.x, v1.y);
        Atf[r0 * ASP + cu]       = *reinterpret_cast<unsigned*>(&lo);
        Atf[(r0 + 8) * ASP + cu] = *reinterpret_cast<unsigned*>(&hi);
    }
    __syncthreads();

    for (int s = 0; s < TLEN - 1; s++) {
        const float hs = tg[s + 1] - tg[s];
        const float h6 = hs * (1.0f / 6.0f);
        const float h3 = hs * (1.0f / 3.0f);
        const float h2 = hs * 0.5f;

        // ---- k1 ----
        feval(Atf, Htf, Wf1, Wf2, bias1, bias2, lane, nt0, r0, c0, kf);
#pragma unroll
        for (int t = 0; t < 2; t++) {
            int cu = (nt0 + t) * 4 + c0;
            float st[4];
#pragma unroll
            for (int d = 0; d < 4; d++) {
                ar[t][d] = fmaf(h6, kf[t][d], zr[t][d]);
                st[d]    = fmaf(h2, kf[t][d], zr[t][d]);
            }
            __half2 lo = __floats2half2_rn(st[0], st[1]);
            __half2 hi = __floats2half2_rn(st[2], st[3]);
            Atf[r0 * ASP + cu]       = *reinterpret_cast<unsigned*>(&lo);
            Atf[(r0 + 8) * ASP + cu] = *reinterpret_cast<unsigned*>(&hi);
        }
        __syncthreads();

        // ---- k2 ----
        feval(Atf, Htf, Wf1, Wf2, bias1, bias2, lane, nt0, r0, c0, kf);
#pragma unroll
        for (int t = 0; t < 2; t++) {
            int cu = (nt0 + t) * 4 + c0;
            float st[4];
#pragma unroll
            for (int d = 0; d < 4; d++) {
                ar[t][d] = fmaf(h3, kf[t][d], ar[t][d]);
                st[d]    = fmaf(h2, kf[t][d], zr[t][d]);
            }
            __half2 lo = __floats2half2_rn(st[0], st[1]);
            __half2 hi = __floats2half2_rn(st[2], st[3]);
            Atf[r0 * ASP + cu]       = *reinterpret_cast<unsigned*>(&lo);
            Atf[(r0 + 8) * ASP + cu] = *reinterpret_cast<unsigned*>(&hi);
        }
        __syncthreads();

        // ---- k3 ----
        feval(Atf, Htf, Wf1, Wf2, bias1, bias2, lane, nt0, r0, c0, kf);
#pragma unroll
        for (int t = 0; t < 2; t++) {
            int cu = (nt0 + t) * 4 + c0;
            float st[4];
#pragma unroll
            for (int d = 0; d < 4; d++) {
                ar[t][d] = fmaf(h3, kf[t][d], ar[t][d]);
                st[d]    = fmaf(hs, kf[t][d], zr[t][d]);
            }
            __half2 lo = __floats2half2_rn(st[0], st[1]);
            __half2 hi = __floats2half2_rn(st[2], st[3]);
            Atf[r0 * ASP + cu]       = *reinterpret_cast<unsigned*>(&lo);
            Atf[(r0 + 8) * ASP + cu] = *reinterpret_cast<unsigned*>(&hi);
        }
        __syncthreads();

        // ---- k4 + state update ----
        feval(Atf, Htf, Wf1, Wf2, bias1, bias2, lane, nt0, r0, c0, kf);
#pragma unroll
        for (int t = 0; t < 2; t++) {
            int cu = (nt0 + t) * 4 + c0;
#pragma unroll
            for (int d = 0; d < 4; d++)
                zr[t][d] = fmaf(h6, kf[t][d], ar[t][d]);
            __half2 lo = __floats2half2_rn(zr[t][0], zr[t][1]);
            __half2 hi = __floats2half2_rn(zr[t][2], zr[t][3]);
            Atf[r0 * ASP + cu]       = *reinterpret_cast<unsigned*>(&lo);
            Atf[(r0 + 8) * ASP + cu] = *reinterpret_cast<unsigned*>(&hi);
        }
        __syncthreads();
    }

#pragma unroll
    for (int t = 0; t < 2; t++) {
        int cb = (nt0 + t) * 8 + 2 * c0;
        float2 v0 = {zr[t][0], zr[t][1]};
        float2 v1 = {zr[t][2], zr[t][3]};
        *reinterpret_cast<float2*>(&out[(row0 + r0) * ZDIM + cb])     = v0;
        *reinterpret_cast<float2*>(&out[(row0 + r0 + 8) * ZDIM + cb]) = v1;
    }
}

extern "C" void kernel_launch(void* const* d_in, const int* in_sizes, int n_in,
                              void* d_out, int out_size)
{
    const float* z0 = (const float*)d_in[0];
    const float* t  = (const float*)d_in[1];
    const float* W1 = (const float*)d_in[2];
    const float* b1 = (const float*)d_in[3];
    const float* W2 = (const float*)d_in[4];
    const float* b2 = (const float*)d_in[5];
    float* out = (float*)d_out;

    prep_kernel<<<(NWREC + 255) / 256, 256>>>(W1, W2);
    node_kernel<<<NCTA, 512>>>(z0, t, b1, b2, out);
}

// round 4
// speedup vs baseline: 4.8790x; 1.2238x over previous
#include <cuda_runtime.h>
#include <cuda_fp16.h>
#include <stdint.h>

// NeuralODE RK4, fp16 mma (m16n8k16, fp32 accum), sm_103a.
// 64 CTAs x 512 threads; CTA owns 16 batch rows for all 127 steps.
// W1 fragments persistent in SMEM (LDS B path, no LDG latency on GEMM1).
// W2 fragments streamed from L1 with a cross-phase register prefetch window
// filled during GEMM1 so GEMM2 never cold-starts after a barrier.

#define ZDIM 256
#define TLEN 128
#define MROW 16
#define NCTA 64
#define NKT  16           // K/16
#define NNT  32           // N/8
#define ASP  132          // A smem row stride in half2 words (conflict-free)
#define WREC (NKT * NNT * 32)          // uint2 records per matrix (16384 = 128KB)

#define SMEM_W1   0
#define SMEM_ATF  (WREC * 8)                       // 131072
#define SMEM_HTF  (SMEM_ATF + MROW * ASP * 4)      // +8448
#define SMEM_TOT  (SMEM_HTF + MROW * ASP * 4)      // ~144.5 KB

__device__ uint2 WfG[2 * WREC];   // fragment-layout fp16 weights (prep output)

// ---- prep: W[k][n] row-major fp32 -> fp16 B-fragment layout ----
__global__ void prep_kernel(const float* __restrict__ W1, const float* __restrict__ W2)
{
    int idx = blockIdx.x * blockDim.x + threadIdx.x;
    if (idx >= 2 * WREC) return;
    int lane = idx & 31;
    int nt   = (idx >> 5) & 31;
    int kt   = (idx >> 10) & 15;
    int g    = idx >> 14;
    const float* W = g ? W2 : W1;
    int k0 = kt * 16 + 2 * (lane & 3);
    int n  = nt * 8 + (lane >> 2);
    __half2 lo = __floats2half2_rn(W[k0 * ZDIM + n],       W[(k0 + 1) * ZDIM + n]);
    __half2 hi = __floats2half2_rn(W[(k0 + 8) * ZDIM + n], W[(k0 + 9) * ZDIM + n]);
    uint2 v;
    v.x = *reinterpret_cast<unsigned*>(&lo);
    v.y = *reinterpret_cast<unsigned*>(&hi);
    WfG[idx] = v;
}

#define MMA16(ACC, A0, A1, A2, A3, B) \
    asm volatile("mma.sync.aligned.m16n8k16.row.col.f32.f16.f16.f32 " \
                 "{%0,%1,%2,%3}, {%4,%5,%6,%7}, {%8,%9}, {%0,%1,%2,%3};" \
                 : "+f"(ACC[0]), "+f"(ACC[1]), "+f"(ACC[2]), "+f"(ACC[3]) \
                 : "r"(A0), "r"(A1), "r"(A2), "r"(A3), "r"(B.x), "r"(B.y))

// GEMM1: B from SMEM (W1); also fills the 8-deep W2 prefetch window.
__device__ __forceinline__ void gemm_s(const unsigned* __restrict__ As,
                                       const uint2* __restrict__ w1s,
                                       const uint2* __restrict__ w2g,
                                       uint2 w2win[8][2],
                                       int lane, int nt0,
                                       const float bias[2][2], float acc[2][4])
{
    const int r0 = lane >> 2;
    const int c0 = lane & 3;
#pragma unroll
    for (int t = 0; t < 2; t++) {
        acc[t][0] = bias[t][0]; acc[t][1] = bias[t][1];
        acc[t][2] = bias[t][0]; acc[t][3] = bias[t][1];
    }

    unsigned a0 = As[r0 * ASP + c0];
    unsigned a1 = As[(r0 + 8) * ASP + c0];
    unsigned a2 = As[r0 * ASP + c0 + 4];
    unsigned a3 = As[(r0 + 8) * ASP + c0 + 4];

#pragma unroll
    for (int kt = 0; kt < NKT; kt++) {
        // W2 prefetch for the upcoming GEMM2 (independent of this GEMM's data)
        if (kt < 8) {
            w2win[kt][0] = w2g[(kt * NNT + nt0) * 32 + lane];
            w2win[kt][1] = w2g[(kt * NNT + nt0 + 1) * 32 + lane];
        }
        uint2 b0 = w1s[(kt * NNT + nt0) * 32 + lane];
        uint2 b1 = w1s[(kt * NNT + nt0 + 1) * 32 + lane];
        unsigned n0, n1, n2, n3;
        if (kt + 1 < NKT) {
            const unsigned* An = As + (kt + 1) * 8;
            n0 = An[r0 * ASP + c0];
            n1 = An[(r0 + 8) * ASP + c0];
            n2 = An[r0 * ASP + c0 + 4];
            n3 = An[(r0 + 8) * ASP + c0 + 4];
        }
        MMA16(acc[0], a0, a1, a2, a3, b0);
        MMA16(acc[1], a0, a1, a2, a3, b1);
        a0 = n0; a1 = n1; a2 = n2; a3 = n3;
    }
}

// GEMM2: B from the register window (refilled in-loop 8 ahead).
__device__ __forceinline__ void gemm_r(const unsigned* __restrict__ As,
                                       const uint2* __restrict__ w2g,
                                       uint2 w2win[8][2],
                                       int lane, int nt0,
                                       const float bias[2][2], float acc[2][4])
{
    const int r0 = lane >> 2;
    const int c0 = lane & 3;
#pragma unroll
    for (int t = 0; t < 2; t++) {
        acc[t][0] = bias[t][0]; acc[t][1] = bias[t][1];
        acc[t][2] = bias[t][0]; acc[t][3] = bias[t][1];
    }

    unsigned a0 = As[r0 * ASP + c0];
    unsigned a1 = As[(r0 + 8) * ASP + c0];
    unsigned a2 = As[r0 * ASP + c0 + 4];
    unsigned a3 = As[(r0 + 8) * ASP + c0 + 4];

#pragma unroll
    for (int kt = 0; kt < NKT; kt++) {
        uint2 b0 = w2win[kt & 7][0];
        uint2 b1 = w2win[kt & 7][1];
        if (kt < 8) {
            w2win[kt][0] = w2g[((kt + 8) * NNT + nt0) * 32 + lane];
            w2win[kt][1] = w2g[((kt + 8) * NNT + nt0 + 1) * 32 + lane];
        }
        unsigned n0, n1, n2, n3;
        if (kt + 1 < NKT) {
            const unsigned* An = As + (kt + 1) * 8;
            n0 = An[r0 * ASP + c0];
            n1 = An[(r0 + 8) * ASP + c0];
            n2 = An[r0 * ASP + c0 + 4];
            n3 = An[(r0 + 8) * ASP + c0 + 4];
        }
        MMA16(acc[0], a0, a1, a2, a3, b0);
        MMA16(acc[1], a0, a1, a2, a3, b1);
        a0 = n0; a1 = n1; a2 = n2; a3 = n3;
    }
}

__global__ void __launch_bounds__(512, 1)
node_kernel(const float* __restrict__ z0, const float* __restrict__ tg,
            const float* __restrict__ b1, const float* __restrict__ b2,
            float* __restrict__ out)
{
    extern __shared__ unsigned char smem_raw[];
    uint2*    w1s = reinterpret_cast<uint2*>(smem_raw + SMEM_W1);
    unsigned* Atf = reinterpret_cast<unsigned*>(smem_raw + SMEM_ATF);
    unsigned* Htf = reinterpret_cast<unsigned*>(smem_raw + SMEM_HTF);

    const int tid  = threadIdx.x;
    const int lane = tid & 31;
    const int wid  = tid >> 5;
    const int nt0  = wid * 2;
    const int r0   = lane >> 2;
    const int c0   = lane & 3;
    const int row0 = blockIdx.x * MROW;

    const uint2* w2g = WfG + WREC;

    // Load W1 fragments into SMEM once (coalesced, L2 hits).
#pragma unroll
    for (int i = 0; i < WREC / 512; i++)
        w1s[i * 512 + tid] = WfG[i * 512 + tid];

    float bias1[2][2], bias2[2][2];
#pragma unroll
    for (int t = 0; t < 2; t++) {
        int cb = (nt0 + t) * 8 + 2 * c0;
        bias1[t][0] = b1[cb]; bias1[t][1] = b1[cb + 1];
        bias2[t][0] = b2[cb]; bias2[t][1] = b2[cb + 1];
    }

    float zr[2][4], ar[2][4], kf[2][4];
    uint2 w2win[8][2];
#pragma unroll
    for (int t = 0; t < 2; t++) {
        int cb = (nt0 + t) * 8 + 2 * c0;
        float2 v0 = *reinterpret_cast<const float2*>(&z0[(row0 + r0) * ZDIM + cb]);
        float2 v1 = *reinterpret_cast<const float2*>(&z0[(row0 + r0 + 8) * ZDIM + cb]);
        zr[t][0] = v0.x; zr[t][1] = v0.y; zr[t][2] = v1.x; zr[t][3] = v1.y;
        int cu = (nt0 + t) * 4 + c0;
        __half2 lo = __floats2half2_rn(v0.x, v0.y);
        __half2 hi = __floats2half2_rn(v1.x, v1.y);
        Atf[r0 * ASP + cu]       = *reinterpret_cast<unsigned*>(&lo);
        Atf[(r0 + 8) * ASP + cu] = *reinterpret_cast<unsigned*>(&hi);
    }
    __syncthreads();

#define FEVAL()                                                             \
    do {                                                                    \
        float acc[2][4];                                                    \
        gemm_s(Atf, w1s, w2g, w2win, lane, nt0, bias1, acc);                \
        _Pragma("unroll")                                                   \
        for (int t = 0; t < 2; t++) {                                       \
            int cu = (nt0 + t) * 4 + c0;                                    \
            __half2 lo = __floats2half2_rn(tanhf(acc[t][0]), tanhf(acc[t][1])); \
            __half2 hi = __floats2half2_rn(tanhf(acc[t][2]), tanhf(acc[t][3])); \
            Htf[r0 * ASP + cu]       = *reinterpret_cast<unsigned*>(&lo);   \
            Htf[(r0 + 8) * ASP + cu] = *reinterpret_cast<unsigned*>(&hi);   \
        }                                                                   \
        __syncthreads();                                                    \
        gemm_r(Htf, w2g, w2win, lane, nt0, bias2, kf);                      \
    } while (0)

    for (int s = 0; s < TLEN - 1; s++) {
        const float hs = tg[s + 1] - tg[s];
        const float h6 = hs * (1.0f / 6.0f);
        const float h3 = hs * (1.0f / 3.0f);
        const float h2 = hs * 0.5f;

        // ---- k1 ----
        FEVAL();
#pragma unroll
        for (int t = 0; t < 2; t++) {
            int cu = (nt0 + t) * 4 + c0;
            float st[4];
#pragma unroll
            for (int d = 0; d < 4; d++) {
                ar[t][d] = fmaf(h6, kf[t][d], zr[t][d]);
                st[d]    = fmaf(h2, kf[t][d], zr[t][d]);
            }
            __half2 lo = __floats2half2_rn(st[0], st[1]);
            __half2 hi = __floats2half2_rn(st[2], st[3]);
            Atf[r0 * ASP + cu]       = *reinterpret_cast<unsigned*>(&lo);
            Atf[(r0 + 8) * ASP + cu] = *reinterpret_cast<unsigned*>(&hi);
        }
        __syncthreads();

        // ---- k2 ----
        FEVAL();
#pragma unroll
        for (int t = 0; t < 2; t++) {
            int cu = (nt0 + t) * 4 + c0;
            float st[4];
#pragma unroll
            for (int d = 0; d < 4; d++) {
                ar[t][d] = fmaf(h3, kf[t][d], ar[t][d]);
                st[d]    = fmaf(h2, kf[t][d], zr[t][d]);
            }
            __half2 lo = __floats2half2_rn(st[0], st[1]);
            __half2 hi = __floats2half2_rn(st[2], st[3]);
            Atf[r0 * ASP + cu]       = *reinterpret_cast<unsigned*>(&lo);
            Atf[(r0 + 8) * ASP + cu] = *reinterpret_cast<unsigned*>(&hi);
        }
        __syncthreads();

        // ---- k3 ----
        FEVAL();
#pragma unroll
        for (int t = 0; t < 2; t++) {
            int cu = (nt0 + t) * 4 + c0;
            float st[4];
#pragma unroll
            for (int d = 0; d < 4; d++) {
                ar[t][d] = fmaf(h3, kf[t][d], ar[t][d]);
                st[d]    = fmaf(hs, kf[t][d], zr[t][d]);
            }
            __half2 lo = __floats2half2_rn(st[0], st[1]);
            __half2 hi = __floats2half2_rn(st[2], st[3]);
            Atf[r0 * ASP + cu]       = *reinterpret_cast<unsigned*>(&lo);
            Atf[(r0 + 8) * ASP + cu] = *reinterpret_cast<unsigned*>(&hi);
        }
        __syncthreads();

        // ---- k4 + state update ----
        FEVAL();
#pragma unroll
        for (int t = 0; t < 2; t++) {
            int cu = (nt0 + t) * 4 + c0;
#pragma unroll
            for (int d = 0; d < 4; d++)
                zr[t][d] = fmaf(h6, kf[t][d], ar[t][d]);
            __half2 lo = __floats2half2_rn(zr[t][0], zr[t][1]);
            __half2 hi = __floats2half2_rn(zr[t][2], zr[t][3]);
            Atf[r0 * ASP + cu]       = *reinterpret_cast<unsigned*>(&lo);
            Atf[(r0 + 8) * ASP + cu] = *reinterpret_cast<unsigned*>(&hi);
        }
        __syncthreads();
    }

#pragma unroll
    for (int t = 0; t < 2; t++) {
        int cb = (nt0 + t) * 8 + 2 * c0;
        float2 v0 = {zr[t][0], zr[t][1]};
        float2 v1 = {zr[t][2], zr[t][3]};
        *reinterpret_cast<float2*>(&out[(row0 + r0) * ZDIM + cb])     = v0;
        *reinterpret_cast<float2*>(&out[(row0 + r0 + 8) * ZDIM + cb]) = v1;
    }
}

extern "C" void kernel_launch(void* const* d_in, const int* in_sizes, int n_in,
                              void* d_out, int out_size)
{
    const float* z0 = (const float*)d_in[0];
    const float* t  = (const float*)d_in[1];
    const float* W1 = (const float*)d_in[2];
    const float* b1 = (const float*)d_in[3];
    const float* W2 = (const float*)d_in[4];
    const float* b2 = (const float*)d_in[5];
    float* out = (float*)d_out;

    cudaFuncSetAttribute(node_kernel,
                         cudaFuncAttributeMaxDynamicSharedMemorySize, SMEM_TOT);

    prep_kernel<<<(2 * WREC + 255) / 256, 256>>>(W1, W2);
    node_kernel<<<NCTA, 512, SMEM_TOT>>>(z0, t, b1, b2, out);
}

// round 5
// speedup vs baseline: 7.7500x; 1.5884x over previous
#include <cuda_runtime.h>
#include <cuda_fp16.h>
#include <stdint.h>

// NeuralODE RK4, fp16 mma (m16n8k16, fp32 accum), sm_103a.
// 64 CTAs x 256 threads (8 warps); CTA owns 16 batch rows for 127 steps.
// Crossbar-byte-minimized: 8 warps x 4 n-tiles (A redundancy halved vs R4),
// W1 fragments in SMEM, W2 fragments PERSISTENT IN REGISTERS (zero B-bytes
// for GEMM2), tanh via single-MUFU tanh.approx.f32.

#define ZDIM 256
#define TLEN 128
#define MROW 16
#define NCTA 64
#define NKT  16           // K/16
#define NNT  32           // N/8
#define ASP  132          // A smem row stride in half2 words (conflict-free)
#define WREC (NKT * NNT * 32)          // uint2 records per matrix (128KB)

#define SMEM_W1   0
#define SMEM_ATF  (WREC * 8)                       // 131072
#define SMEM_HTF  (SMEM_ATF + MROW * ASP * 4)
#define SMEM_TOT  (SMEM_HTF + MROW * ASP * 4)      // ~144.5 KB

__device__ uint2 WfG[2 * WREC];   // fragment-layout fp16 weights (prep output)

// ---- prep: W[k][n] row-major fp32 -> fp16 B-fragment layout ----
__global__ void prep_kernel(const float* __restrict__ W1, const float* __restrict__ W2)
{
    int idx = blockIdx.x * blockDim.x + threadIdx.x;
    if (idx >= 2 * WREC) return;
    int lane = idx & 31;
    int nt   = (idx >> 5) & 31;
    int kt   = (idx >> 10) & 15;
    int g    = idx >> 14;
    const float* W = g ? W2 : W1;
    int k0 = kt * 16 + 2 * (lane & 3);
    int n  = nt * 8 + (lane >> 2);
    __half2 lo = __floats2half2_rn(W[k0 * ZDIM + n],       W[(k0 + 1) * ZDIM + n]);
    __half2 hi = __floats2half2_rn(W[(k0 + 8) * ZDIM + n], W[(k0 + 9) * ZDIM + n]);
    uint2 v;
    v.x = *reinterpret_cast<unsigned*>(&lo);
    v.y = *reinterpret_cast<unsigned*>(&hi);
    WfG[idx] = v;
}

#define MMA16(ACC, A0, A1, A2, A3, B) \
    asm volatile("mma.sync.aligned.m16n8k16.row.col.f32.f16.f16.f32 " \
                 "{%0,%1,%2,%3}, {%4,%5,%6,%7}, {%8,%9}, {%0,%1,%2,%3};" \
                 : "+f"(ACC[0]), "+f"(ACC[1]), "+f"(ACC[2]), "+f"(ACC[3]) \
                 : "r"(A0), "r"(A1), "r"(A2), "r"(A3), "r"(B.x), "r"(B.y))

__device__ __forceinline__ float fast_tanh(float x) {
    float y;
    asm("tanh.approx.f32 %0, %1;" : "=f"(y) : "f"(x));
    return y;
}

// GEMM1: A from SMEM, B (W1) from SMEM. acc[4][4] over this warp's 4 n-tiles.
__device__ __forceinline__ void gemm_w1(const unsigned* __restrict__ As,
                                        const uint2* __restrict__ w1s,
                                        int lane, int nt0,
                                        const float bias[4][2], float acc[4][4])
{
    const int r0 = lane >> 2;
    const int c0 = lane & 3;
#pragma unroll
    for (int t = 0; t < 4; t++) {
        acc[t][0] = bias[t][0]; acc[t][1] = bias[t][1];
        acc[t][2] = bias[t][0]; acc[t][3] = bias[t][1];
    }

    unsigned a0 = As[r0 * ASP + c0];
    unsigned a1 = As[(r0 + 8) * ASP + c0];
    unsigned a2 = As[r0 * ASP + c0 + 4];
    unsigned a3 = As[(r0 + 8) * ASP + c0 + 4];
    uint2 b[4];
#pragma unroll
    for (int t = 0; t < 4; t++) b[t] = w1s[(nt0 + t) * 32 + lane];

#pragma unroll
    for (int kt = 0; kt < NKT; kt++) {
        unsigned n0, n1, n2, n3;
        uint2 bn[4];
        if (kt + 1 < NKT) {
            const unsigned* An = As + (kt + 1) * 8;
            n0 = An[r0 * ASP + c0];
            n1 = An[(r0 + 8) * ASP + c0];
            n2 = An[r0 * ASP + c0 + 4];
            n3 = An[(r0 + 8) * ASP + c0 + 4];
#pragma unroll
            for (int t = 0; t < 4; t++)
                bn[t] = w1s[((kt + 1) * NNT + nt0 + t) * 32 + lane];
        }
        MMA16(acc[0], a0, a1, a2, a3, b[0]);
        MMA16(acc[1], a0, a1, a2, a3, b[1]);
        MMA16(acc[2], a0, a1, a2, a3, b[2]);
        MMA16(acc[3], a0, a1, a2, a3, b[3]);
        a0 = n0; a1 = n1; a2 = n2; a3 = n3;
#pragma unroll
        for (int t = 0; t < 4; t++) b[t] = bn[t];
    }
}

// GEMM2: A from SMEM, B (W2) from persistent registers — zero B loads.
__device__ __forceinline__ void gemm_w2(const unsigned* __restrict__ As,
                                        const uint2 w2r[NKT][4],
                                        int lane,
                                        const float bias[4][2], float acc[4][4])
{
    const int r0 = lane >> 2;
    const int c0 = lane & 3;
#pragma unroll
    for (int t = 0; t < 4; t++) {
        acc[t][0] = bias[t][0]; acc[t][1] = bias[t][1];
        acc[t][2] = bias[t][0]; acc[t][3] = bias[t][1];
    }

    unsigned a0 = As[r0 * ASP + c0];
    unsigned a1 = As[(r0 + 8) * ASP + c0];
    unsigned a2 = As[r0 * ASP + c0 + 4];
    unsigned a3 = As[(r0 + 8) * ASP + c0 + 4];

#pragma unroll
    for (int kt = 0; kt < NKT; kt++) {
        unsigned n0, n1, n2, n3;
        if (kt + 1 < NKT) {
            const unsigned* An = As + (kt + 1) * 8;
            n0 = An[r0 * ASP + c0];
            n1 = An[(r0 + 8) * ASP + c0];
            n2 = An[r0 * ASP + c0 + 4];
            n3 = An[(r0 + 8) * ASP + c0 + 4];
        }
        MMA16(acc[0], a0, a1, a2, a3, w2r[kt][0]);
        MMA16(acc[1], a0, a1, a2, a3, w2r[kt][1]);
        MMA16(acc[2], a0, a1, a2, a3, w2r[kt][2]);
        MMA16(acc[3], a0, a1, a2, a3, w2r[kt][3]);
        a0 = n0; a1 = n1; a2 = n2; a3 = n3;
    }
}

__global__ void __launch_bounds__(256, 1)
node_kernel(const float* __restrict__ z0, const float* __restrict__ tg,
            const float* __restrict__ b1, const float* __restrict__ b2,
            float* __restrict__ out)
{
    extern __shared__ unsigned char smem_raw[];
    uint2*    w1s = reinterpret_cast<uint2*>(smem_raw + SMEM_W1);
    unsigned* Atf = reinterpret_cast<unsigned*>(smem_raw + SMEM_ATF);
    unsigned* Htf = reinterpret_cast<unsigned*>(smem_raw + SMEM_HTF);

    const int tid  = threadIdx.x;
    const int lane = tid & 31;
    const int wid  = tid >> 5;           // 0..7
    const int nt0  = wid * 4;            // 4 n-tiles per warp
    const int r0   = lane >> 2;
    const int c0   = lane & 3;
    const int row0 = blockIdx.x * MROW;

    // ---- W1 fragments -> SMEM (once) ----
    {
        const uint4* src = reinterpret_cast<const uint4*>(WfG);
        uint4* dst = reinterpret_cast<uint4*>(w1s);
#pragma unroll
        for (int i = 0; i < WREC / 2 / 256; i++)
            dst[i * 256 + tid] = src[i * 256 + tid];
    }

    // ---- W2 fragments -> persistent registers (once) ----
    uint2 w2r[NKT][4];
    {
        const uint2* w2g = WfG + WREC;
#pragma unroll
        for (int kt = 0; kt < NKT; kt++)
#pragma unroll
            for (int t = 0; t < 4; t++)
                w2r[kt][t] = w2g[(kt * NNT + nt0 + t) * 32 + lane];
    }

    float bias1[4][2], bias2[4][2];
#pragma unroll
    for (int t = 0; t < 4; t++) {
        int cb = (nt0 + t) * 8 + 2 * c0;
        bias1[t][0] = b1[cb]; bias1[t][1] = b1[cb + 1];
        bias2[t][0] = b2[cb]; bias2[t][1] = b2[cb + 1];
    }

    float zr[4][4], ar[4][4], acc[4][4];
#pragma unroll
    for (int t = 0; t < 4; t++) {
        int cb = (nt0 + t) * 8 + 2 * c0;
        float2 v0 = *reinterpret_cast<const float2*>(&z0[(row0 + r0) * ZDIM + cb]);
        float2 v1 = *reinterpret_cast<const float2*>(&z0[(row0 + r0 + 8) * ZDIM + cb]);
        zr[t][0] = v0.x; zr[t][1] = v0.y; zr[t][2] = v1.x; zr[t][3] = v1.y;
        int cu = (nt0 + t) * 4 + c0;
        __half2 lo = __floats2half2_rn(v0.x, v0.y);
        __half2 hi = __floats2half2_rn(v1.x, v1.y);
        Atf[r0 * ASP + cu]       = *reinterpret_cast<unsigned*>(&lo);
        Atf[(r0 + 8) * ASP + cu] = *reinterpret_cast<unsigned*>(&hi);
    }
    __syncthreads();

    // f(z): GEMM1(W1,SMEM B) -> tanh -> Htf -> sync -> GEMM2(W2,reg B) -> acc
#define FEVAL()                                                                 \
    do {                                                                        \
        gemm_w1(Atf, w1s, lane, nt0, bias1, acc);                               \
        _Pragma("unroll")                                                       \
        for (int t = 0; t < 4; t++) {                                           \
            int cu = (nt0 + t) * 4 + c0;                                        \
            __half2 lo = __floats2half2_rn(fast_tanh(acc[t][0]),                \
                                           fast_tanh(acc[t][1]));               \
            __half2 hi = __floats2half2_rn(fast_tanh(acc[t][2]),                \
                                           fast_tanh(acc[t][3]));               \
            Htf[r0 * ASP + cu]       = *reinterpret_cast<unsigned*>(&lo);       \
            Htf[(r0 + 8) * ASP + cu] = *reinterpret_cast<unsigned*>(&hi);       \
        }                                                                       \
        __syncthreads();                                                        \
        gemm_w2(Htf, w2r, lane, bias2, acc);                                    \
    } while (0)

    for (int s = 0; s < TLEN - 1; s++) {
        const float hs = tg[s + 1] - tg[s];
        const float h6 = hs * (1.0f / 6.0f);
        const float h3 = hs * (1.0f / 3.0f);
        const float h2 = hs * 0.5f;

        // ---- k1 ----
        FEVAL();
#pragma unroll
        for (int t = 0; t < 4; t++) {
            int cu = (nt0 + t) * 4 + c0;
            float st[4];
#pragma unroll
            for (int d = 0; d < 4; d++) {
                ar[t][d] = fmaf(h6, acc[t][d], zr[t][d]);
                st[d]    = fmaf(h2, acc[t][d], zr[t][d]);
            }
            __half2 lo = __floats2half2_rn(st[0], st[1]);
            __half2 hi = __floats2half2_rn(st[2], st[3]);
            Atf[r0 * ASP + cu]       = *reinterpret_cast<unsigned*>(&lo);
            Atf[(r0 + 8) * ASP + cu] = *reinterpret_cast<unsigned*>(&hi);
        }
        __syncthreads();

        // ---- k2 ----
        FEVAL();
#pragma unroll
        for (int t = 0; t < 4; t++) {
            int cu = (nt0 + t) * 4 + c0;
            float st[4];
#pragma unroll
            for (int d = 0; d < 4; d++) {
                ar[t][d] = fmaf(h3, acc[t][d], ar[t][d]);
                st[d]    = fmaf(h2, acc[t][d], zr[t][d]);
            }
            __half2 lo = __floats2half2_rn(st[0], st[1]);
            __half2 hi = __floats2half2_rn(st[2], st[3]);
            Atf[r0 * ASP + cu]       = *reinterpret_cast<unsigned*>(&lo);
            Atf[(r0 + 8) * ASP + cu] = *reinterpret_cast<unsigned*>(&hi);
        }
        __syncthreads();

        // ---- k3 ----
        FEVAL();
#pragma unroll
        for (int t = 0; t < 4; t++) {
            int cu = (nt0 + t) * 4 + c0;
            float st[4];
#pragma unroll
            for (int d = 0; d < 4; d++) {
                ar[t][d] = fmaf(h3, acc[t][d], ar[t][d]);
                st[d]    = fmaf(hs, acc[t][d], zr[t][d]);
            }
            __half2 lo = __floats2half2_rn(st[0], st[1]);
            __half2 hi = __floats2half2_rn(st[2], st[3]);
            Atf[r0 * ASP + cu]       = *reinterpret_cast<unsigned*>(&lo);
            Atf[(r0 + 8) * ASP + cu] = *reinterpret_cast<unsigned*>(&hi);
        }
        __syncthreads();

        // ---- k4 + state update ----
        FEVAL();
#pragma unroll
        for (int t = 0; t < 4; t++) {
            int cu = (nt0 + t) * 4 + c0;
#pragma unroll
            for (int d = 0; d < 4; d++)
                zr[t][d] = fmaf(h6, acc[t][d], ar[t][d]);
            __half2 lo = __floats2half2_rn(zr[t][0], zr[t][1]);
            __half2 hi = __floats2half2_rn(zr[t][2], zr[t][3]);
            Atf[r0 * ASP + cu]       = *reinterpret_cast<unsigned*>(&lo);
            Atf[(r0 + 8) * ASP + cu] = *reinterpret_cast<unsigned*>(&hi);
        }
        __syncthreads();
    }

#pragma unroll
    for (int t = 0; t < 4; t++) {
        int cb = (nt0 + t) * 8 + 2 * c0;
        float2 v0 = {zr[t][0], zr[t][1]};
        float2 v1 = {zr[t][2], zr[t][3]};
        *reinterpret_cast<float2*>(&out[(row0 + r0) * ZDIM + cb])     = v0;
        *reinterpret_cast<float2*>(&out[(row0 + r0 + 8) * ZDIM + cb]) = v1;
    }
}

extern "C" void kernel_launch(void* const* d_in, const int* in_sizes, int n_in,
                              void* d_out, int out_size)
{
    const float* z0 = (const float*)d_in[0];
    const float* t  = (const float*)d_in[1];
    const float* W1 = (const float*)d_in[2];
    const float* b1 = (const float*)d_in[3];
    const float* W2 = (const float*)d_in[4];
    const float* b2 = (const float*)d_in[5];
    float* out = (float*)d_out;

    cudaFuncSetAttribute(node_kernel,
                         cudaFuncAttributeMaxDynamicSharedMemorySize, SMEM_TOT);

    prep_kernel<<<(2 * WREC + 255) / 256, 256>>>(W1, W2);
    node_kernel<<<NCTA, 256, SMEM_TOT>>>(z0, t, b1, b2, out);
}